// round 9
// baseline (speedup 1.0000x reference)
#include <cuda_runtime.h>
#include <math.h>

// Problem constants: N=4, P1=P2=2048, D=64
#define NB 4
#define PP 2048
#define DD 64
#define SCL      14.426950408889634f   // INV_EPS * log2(e)
#define ELN2     0.0693147180559945f   // EPSR * ln(2)
#define UC0      (-0.76245985f)        // EPSR * log(1/2048 + 1e-8)
#define THRESHV  0.1f
#define MAXIT    50
#define NBLK     128
#define NT       1024
#define NPITEMS  (NB * PP * PP)
#define MNEG     (-3.402823466e38f)

// ---------------- device scratch (no allocations allowed) ------------------
__device__ float g_XS[NB * PP * DD];     // x @ (M+M^T)
__device__ float g_dx[NB * PP];
__device__ float g_dy[NB * PP];
__device__ float g_u[NB * PP];
__device__ float g_v[NB * PP];
__device__ float g_duabs[NB * PP];
__device__ float2 g_pms[NB * PP * 32];   // col partials [n][col][block] = (m,s)
__device__ float g_cpart[NBLK];
__device__ unsigned g_bar_count;
__device__ volatile unsigned g_bar_gen;

__device__ __forceinline__ float ex2f(float x) {
    float r;
    asm("ex2.approx.ftz.f32 %0, %1;" : "=f"(r) : "f"(x));
    return r;
}

// online-LSE merge in log2 domain, single ex2
__device__ __forceinline__ void lse_merge2(float& m, float& s, float mc, float sc) {
    float mmax = fmaxf(m, mc);
    float e = ex2f(fminf(m, mc) - mmax);
    s = (m >= mc) ? fmaf(sc, e, s) : fmaf(s, e, sc);
    m = mmax;
}

// ---------------- software grid barrier (all NBLK blocks resident) ---------
__device__ __forceinline__ void grid_bar() {
    __syncthreads();
    if (threadIdx.x == 0) {
        __threadfence();
        unsigned gen = g_bar_gen;
        if (atomicAdd(&g_bar_count, 1u) == NBLK - 1) {
            g_bar_count = 0;
            __threadfence();
            g_bar_gen = gen + 1;
        } else {
            while (g_bar_gen == gen) __nanosleep(32);
        }
        __threadfence();
    }
    __syncthreads();
}

__global__ void __launch_bounds__(NT, 1)
sinkhorn_all(const float* __restrict__ x, const float* __restrict__ y,
             const float* __restrict__ Mm,
             float* __restrict__ cost, float* __restrict__ pi,
             float* __restrict__ C)
{
    // unified smem pool (44KB):
    //  gemm/prep: sa = pool[0..4223], sb = pool[4224..8447]
    //  iter:      se = pool[0..8191] (4 rows x 2048 z values), sv = pool[8192..10239]
    //  fin:       fsu = pool[0..63], fred = pool[1024..2047], sv = pool[8192..]
    __shared__ __align__(16) float pool[11264];
    __shared__ float pmax[32], psum[32], srow[4];
    __shared__ float s_err[1];

    float* const sa = pool;
    float* const sb = pool + 4224;
    float* const se = pool;
    float* const sv = pool + 8192;

    const int t    = threadIdx.x;
    const int b    = blockIdx.x;
    const int lane = t & 31;
    const int w    = t >> 5;

    // ---- phase 0: zero u, v slice -----------------------------------------
    if (t < 64) {
        g_u[(b << 6) + t] = 0.0f;
        g_v[(b << 6) + t] = 0.0f;
    }

    // ---- phase 1: S = M + M^T ---------------------------------------------
    for (int idx = t; idx < DD * DD; idx += NT) {
        int d = idx >> 6, e = idx & 63;
        sa[idx] = Mm[idx] + Mm[(e << 6) + d];
    }
    __syncthreads();

    // ---- phase 2: XS = x@S, dx = xMx^T, dy = yMy^T ------------------------
    for (int half = 0; half < 2; half++) {
        const float* src = half ? y : x;
        for (int batch = 0; batch < 4; batch++) {
            int row0 = (b << 6) + (batch << 4);
            __syncthreads();
            sb[t] = src[(size_t)row0 * DD + t];
            __syncthreads();
            int slot = t >> 6, e = t & 63;
            float acc = 0.0f;
            #pragma unroll 16
            for (int d = 0; d < DD; d++)
                acc = fmaf(sa[(d << 6) + e], sb[(slot << 6) + d], acc);
            int row = row0 + slot;
            if (!half) g_XS[(size_t)row * DD + e] = acc;
            sb[1024 + t] = acc * sb[(slot << 6) + e];
            __syncthreads();
            for (int off = 32; off > 0; off >>= 1) {
                if (e < off) sb[1024 + (slot << 6) + e] += sb[1024 + (slot << 6) + e + off];
                __syncthreads();
            }
            if (e == 0) {
                float dv = 0.5f * sb[1024 + (slot << 6)];
                if (!half) g_dx[row] = dv; else g_dy[row] = dv;
            }
        }
    }

    grid_bar();

    // ---- phase 3: C build. 128x128 tiles ----------------------------------
    for (int tt = 0; tt < 8; tt++) {
        int tile = b + (tt << 7);
        int n  = tile >> 8;
        int rem = tile & 255;
        int i0 = (rem >> 4) << 7;
        int j0 = (rem & 15) << 7;
        float acc[16];
        #pragma unroll
        for (int q = 0; q < 16; q++) acc[q] = 0.0f;

        #pragma unroll
        for (int ks = 0; ks < 64; ks += 32) {
            __syncthreads();
            {
                int i = t >> 3, kq = t & 7;
                float4 xa = *(const float4*)(g_XS + (size_t)(n * PP + i0 + i) * DD + ks + (kq << 2));
                float4 yb = *(const float4*)(y    + (size_t)(n * PP + j0 + i) * DD + ks + (kq << 2));
                int k0 = kq << 2;
                sa[(k0+0)*132 + i] = xa.x;  sa[(k0+1)*132 + i] = xa.y;
                sa[(k0+2)*132 + i] = xa.z;  sa[(k0+3)*132 + i] = xa.w;
                sb[(k0+0)*132 + i] = yb.x;  sb[(k0+1)*132 + i] = yb.y;
                sb[(k0+2)*132 + i] = yb.z;  sb[(k0+3)*132 + i] = yb.w;
            }
            __syncthreads();
            int cx = t & 31, cy = t >> 5;
            #pragma unroll
            for (int k = 0; k < 32; k++) {
                float4 a4 = *(const float4*)&sa[k*132 + (cy << 2)];
                float4 b4 = *(const float4*)&sb[k*132 + (cx << 2)];
                acc[ 0] = fmaf(a4.x, b4.x, acc[ 0]);
                acc[ 1] = fmaf(a4.x, b4.y, acc[ 1]);
                acc[ 2] = fmaf(a4.x, b4.z, acc[ 2]);
                acc[ 3] = fmaf(a4.x, b4.w, acc[ 3]);
                acc[ 4] = fmaf(a4.y, b4.x, acc[ 4]);
                acc[ 5] = fmaf(a4.y, b4.y, acc[ 5]);
                acc[ 6] = fmaf(a4.y, b4.z, acc[ 6]);
                acc[ 7] = fmaf(a4.y, b4.w, acc[ 7]);
                acc[ 8] = fmaf(a4.z, b4.x, acc[ 8]);
                acc[ 9] = fmaf(a4.z, b4.y, acc[ 9]);
                acc[10] = fmaf(a4.z, b4.z, acc[10]);
                acc[11] = fmaf(a4.z, b4.w, acc[11]);
                acc[12] = fmaf(a4.w, b4.x, acc[12]);
                acc[13] = fmaf(a4.w, b4.y, acc[13]);
                acc[14] = fmaf(a4.w, b4.z, acc[14]);
                acc[15] = fmaf(a4.w, b4.w, acc[15]);
            }
        }
        int cx = t & 31, cy = t >> 5;
        float dxr[4], dyr[4];
        #pragma unroll
        for (int q = 0; q < 4; q++) {
            dxr[q] = g_dx[n * PP + i0 + (cy << 2) + q];
            dyr[q] = g_dy[n * PP + j0 + (cx << 2) + q];
        }
        #pragma unroll
        for (int a = 0; a < 4; a++) {
            float4 o;
            o.x = dxr[a] + dyr[0] - acc[(a << 2) + 0];
            o.y = dxr[a] + dyr[1] - acc[(a << 2) + 1];
            o.z = dxr[a] + dyr[2] - acc[(a << 2) + 2];
            o.w = dxr[a] + dyr[3] - acc[(a << 2) + 3];
            *(float4*)(C + (size_t)(n * PP + i0 + (cy << 2) + a) * PP + j0 + (cx << 2)) = o;
        }
    }

    grid_bar();

    // ---- phase 4: Sinkhorn iterations, single C read per iteration --------
    const int n_pass = b >> 5;
    const int sub    = b & 31;
    const float* Cn  = C + ((size_t)n_pass << 22);
    const float4* C4n = (const float4*)Cn;
    bool active = true;

    for (int it = 0; it < MAXIT; it++) {
        // stage scaled v2 = v*SCL
        sv[t]        = g_v[(n_pass << 11) + t] * SCL;
        sv[t + 1024] = g_v[(n_pass << 11) + 1024 + t] * SCL;
        __syncthreads();
        const float4* vs4 = (const float4*)sv;

        float cm0 = MNEG, cs0 = 0.0f;    // col accumulators: col t
        float cm1 = MNEG, cs1 = 0.0f;    // col t+1024

        const int rr  = t >> 8;          // row within 4-row band
        const int cth = t & 255;         // float4 index within half-row

        #pragma unroll 1
        for (int band = 0; band < 16; band++) {
            int r0 = (sub << 6) + (band << 2);
            // ===== row phase: z = v2 - C*SCL, store z, exact row max =======
            const float4* Cr = C4n + (size_t)(r0 + rr) * 512;
            float4 ca = Cr[cth];
            float4 cb = Cr[cth + 256];
            float4 va = vs4[cth];
            float4 vb = vs4[cth + 256];
            float z0 = fmaf(ca.x, -SCL, va.x);
            float z1 = fmaf(ca.y, -SCL, va.y);
            float z2 = fmaf(ca.z, -SCL, va.z);
            float z3 = fmaf(ca.w, -SCL, va.w);
            float z4 = fmaf(cb.x, -SCL, vb.x);
            float z5 = fmaf(cb.y, -SCL, vb.y);
            float z6 = fmaf(cb.z, -SCL, vb.z);
            float z7 = fmaf(cb.w, -SCL, vb.w);
            float4 zv0; zv0.x = z0; zv0.y = z1; zv0.z = z2; zv0.w = z3;
            float4 zv1; zv1.x = z4; zv1.y = z5; zv1.z = z6; zv1.w = z7;
            ((float4*)se)[(rr << 9) + cth]       = zv0;
            ((float4*)se)[(rr << 9) + cth + 256] = zv1;
            float mloc = fmaxf(fmaxf(fmaxf(z0, z1), fmaxf(z2, z3)),
                               fmaxf(fmaxf(z4, z5), fmaxf(z6, z7)));
            #pragma unroll
            for (int off = 16; off > 0; off >>= 1)
                mloc = fmaxf(mloc, __shfl_xor_sync(0xffffffffu, mloc, off));
            if (lane == 0) pmax[w] = mloc;
            __syncthreads();
            int wb = rr << 3;
            float mr = fmaxf(fmaxf(fmaxf(pmax[wb], pmax[wb+1]), fmaxf(pmax[wb+2], pmax[wb+3])),
                             fmaxf(fmaxf(pmax[wb+4], pmax[wb+5]), fmaxf(pmax[wb+6], pmax[wb+7])));
            float sloc = ((ex2f(z0 - mr) + ex2f(z1 - mr)) + (ex2f(z2 - mr) + ex2f(z3 - mr)))
                       + ((ex2f(z4 - mr) + ex2f(z5 - mr)) + (ex2f(z6 - mr) + ex2f(z7 - mr)));
            #pragma unroll
            for (int off = 16; off > 0; off >>= 1)
                sloc += __shfl_xor_sync(0xffffffffu, sloc, off);
            if (lane == 0) psum[w] = sloc;
            __syncthreads();
            if (t < 4) {
                int wq = t << 3;
                float sr = ((psum[wq] + psum[wq+1]) + (psum[wq+2] + psum[wq+3]))
                         + ((psum[wq+4] + psum[wq+5]) + (psum[wq+6] + psum[wq+7]));
                float mrow = fmaxf(fmaxf(fmaxf(pmax[wq], pmax[wq+1]), fmaxf(pmax[wq+2], pmax[wq+3])),
                                   fmaxf(fmaxf(pmax[wq+4], pmax[wq+5]), fmaxf(pmax[wq+6], pmax[wq+7])));
                float L = mrow + log2f(sr);
                float unew = UC0 - ELN2 * L;
                int gr = (n_pass << 11) + r0 + t;
                g_duabs[gr] = fabsf(unew - g_u[gr]);
                g_u[gr] = unew;
                srow[t] = unew * SCL;              // u2_i for col phase
            }
            __syncthreads();
            // ===== col phase: per-column max over band (numerically safe) ==
            {
                float u0 = srow[0], u1 = srow[1], u2v = srow[2], u3 = srow[3];
                // col t: xi = z + u2 (the -v2_j constant folds into the merge)
                float a0 = se[t]        + u0;
                float a1 = se[t + 2048] + u1;
                float a2 = se[t + 4096] + u2v;
                float a3 = se[t + 6144] + u3;
                float mc0 = fmaxf(fmaxf(a0, a1), fmaxf(a2, a3));
                float p0  = (ex2f(a0 - mc0) + ex2f(a1 - mc0))
                          + (ex2f(a2 - mc0) + ex2f(a3 - mc0));
                lse_merge2(cm0, cs0, mc0, p0);
                // col t+1024
                float b0 = se[t + 1024] + u0;
                float b1 = se[t + 3072] + u1;
                float b2 = se[t + 5120] + u2v;
                float b3 = se[t + 7168] + u3;
                float mc1 = fmaxf(fmaxf(b0, b1), fmaxf(b2, b3));
                float p1  = (ex2f(b0 - mc1) + ex2f(b1 - mc1))
                          + (ex2f(b2 - mc1) + ex2f(b3 - mc1));
                lse_merge2(cm1, cs1, mc1, p1);
            }
        }
        // write col partials [n][col][block]
        {
            float2 p0; p0.x = cm0; p0.y = cs0;
            float2 p1; p1.x = cm1; p1.y = cs1;
            g_pms[(((size_t)(n_pass << 11) + t) << 5) + sub]         = p0;
            g_pms[(((size_t)(n_pass << 11) + t + 1024) << 5) + sub]  = p1;
        }
        grid_bar();

        // ===== merge: warp per column, coalesced reads + shuffle tree ======
        {
            int j0 = sub << 6;
            #pragma unroll
            for (int rep = 0; rep < 2; rep++) {
                int col = j0 + w + (rep << 5);
                float2 p = g_pms[(((size_t)(n_pass << 11) + col) << 5) + lane];
                float mm = p.x, ss = p.y;
                #pragma unroll
                for (int off = 16; off > 0; off >>= 1) {
                    float mo = __shfl_xor_sync(0xffffffffu, mm, off);
                    float so = __shfl_xor_sync(0xffffffffu, ss, off);
                    lse_merge2(mm, ss, mo, so);
                }
                if (lane == 0) {
                    int gc = (n_pass << 11) + col;
                    // partials computed on (z + u2) basis = true xi + v2_j,
                    // so lse_true = (mm + log2 ss) - v2_j ; ELN2*v2_j = v_old
                    g_v[gc] = UC0 - ELN2 * (mm + log2f(ss)) + g_v[gc];
                }
            }
        }

        // ===== convergence: shuffle-based replicated reduction =============
        {
            float ea = 0.0f;
            #pragma unroll
            for (int q = 0; q < 8; q++) ea += g_duabs[t + (q << 10)];
            #pragma unroll
            for (int off = 16; off > 0; off >>= 1)
                ea += __shfl_xor_sync(0xffffffffu, ea, off);
            if (lane == 0) pmax[w] = ea;
            __syncthreads();
            if (w == 0) {
                float v2 = pmax[lane];
                #pragma unroll
                for (int off = 16; off > 0; off >>= 1)
                    v2 += __shfl_xor_sync(0xffffffffu, v2, off);
                if (lane == 0) s_err[0] = v2;
            }
            __syncthreads();
            active = (s_err[0] * 0.25f >= THRESHV);
        }
        grid_bar();
        if (!active) break;
    }

    // ---- phase 5: pi = exp2(u2+v2-C*SCL), cost partials --------------------
    {
        float* fsu  = pool;          // 64 floats
        float* fred = pool + 1024;   // 1024 floats
        sv[t]        = g_v[(n_pass << 11) + t] * SCL;
        sv[t + 1024] = g_v[(n_pass << 11) + 1024 + t] * SCL;
        if (t < 64) fsu[t] = g_u[(n_pass << 11) + (sub << 6) + t] * SCL;
        __syncthreads();
        const float4* vs4 = (const float4*)sv;
        const float4* Cb4 = C4n + (size_t)(sub << 6) * 512;
        float4* pi4 = (float4*)pi + (size_t)(n_pass * PP + (sub << 6)) * 512;
        float accc = 0.0f;
        #pragma unroll 4
        for (int k2 = 0; k2 < 32; k2++) {
            int idx = t + (k2 << 10);
            int row = idx >> 9;
            int c4  = idx & 511;
            float4 cc = Cb4[(size_t)row * 512 + c4];
            float  uu = fsu[row];
            float4 vv = vs4[c4];
            float p0 = ex2f(fmaf(cc.x, -SCL, uu + vv.x));
            float p1 = ex2f(fmaf(cc.y, -SCL, uu + vv.y));
            float p2 = ex2f(fmaf(cc.z, -SCL, uu + vv.z));
            float p3 = ex2f(fmaf(cc.w, -SCL, uu + vv.w));
            float4 po; po.x = p0; po.y = p1; po.z = p2; po.w = p3;
            pi4[(size_t)row * 512 + c4] = po;
            accc = fmaf(p0, cc.x, accc);
            accc = fmaf(p1, cc.y, accc);
            accc = fmaf(p2, cc.z, accc);
            accc = fmaf(p3, cc.w, accc);
        }
        __syncthreads();
        fred[t] = accc;
        __syncthreads();
        for (int off = 512; off > 0; off >>= 1) {
            if (t < off) fred[t] += fred[t + off];
            __syncthreads();
        }
        if (t == 0) g_cpart[b] = fred[0];
    }
    grid_bar();
    if (b == 0 && t == 0) {
        #pragma unroll
        for (int n = 0; n < NB; n++) {
            float c = 0.0f;
            for (int q = 0; q < 32; q++) c += g_cpart[(n << 5) + q];
            cost[n] = c;
        }
    }
}

// ---------------- launch ---------------------------------------------------
extern "C" void kernel_launch(void* const* d_in, const int* in_sizes, int n_in,
                              void* d_out, int out_size) {
    const float* x = (const float*)d_in[0];   // [N,P1,D]
    const float* y = (const float*)d_in[1];   // [N,P2,D]
    const float* M = (const float*)d_in[2];   // [D,D]
    float* out  = (float*)d_out;              // cost[4] | pi | C
    float* cost = out;
    float* pi   = out + 4;
    float* C    = out + 4 + (size_t)NPITEMS;

    sinkhorn_all<<<NBLK, NT>>>(x, y, M, cost, pi, C);
}

// round 11
// speedup vs baseline: 1.0131x; 1.0131x over previous
#include <cuda_runtime.h>
#include <math.h>

// Problem constants: N=4, P1=P2=2048, D=64
#define NB 4
#define PP 2048
#define DD 64
#define SCL      14.426950408889634f   // INV_EPS * log2(e)
#define ELN2     0.0693147180559945f   // EPSR * ln(2)
#define UC0      (-0.76245985f)        // EPSR * log(1/2048 + 1e-8)
#define THRESHV  0.1f
#define MAXIT    50
#define NBLK     128
#define NT       1024
#define NPITEMS  (NB * PP * PP)
#define MNEG     (-3.402823466e38f)

// ---------------- device scratch (no allocations allowed) ------------------
__device__ float g_XS[NB * PP * DD];     // x @ (M+M^T)
__device__ float g_dx[NB * PP];
__device__ float g_dy[NB * PP];
__device__ float g_u[NB * PP];
__device__ float g_v[NB * PP];
__device__ float g_duabs[NB * PP];
__device__ float2 g_pms[NB * PP * 128];  // col partials [n][col][slot128] = (m,s)
__device__ float g_cpart[NBLK];
__device__ unsigned g_bar_count;
__device__ volatile unsigned g_bar_gen;

__device__ __forceinline__ float ex2f(float x) {
    float r;
    asm("ex2.approx.ftz.f32 %0, %1;" : "=f"(r) : "f"(x));
    return r;
}

// online-LSE merge in log2 domain, single ex2
__device__ __forceinline__ void lse_merge2(float& m, float& s, float mc, float sc) {
    float mmax = fmaxf(m, mc);
    float e = ex2f(fminf(m, mc) - mmax);
    s = (m >= mc) ? fmaf(sc, e, s) : fmaf(s, e, sc);
    m = mmax;
}

// online merge of a single element a (sc == 1): one ex2
__device__ __forceinline__ void col_acc(float& m, float& s, float a) {
    float mmax = fmaxf(m, a);
    float e = ex2f(fminf(m, a) - mmax);
    s = (m >= a) ? (s + e) : fmaf(s, e, 1.0f);
    m = mmax;
}

// ---------------- software grid barrier (all NBLK blocks resident) ---------
__device__ __forceinline__ void grid_bar() {
    __syncthreads();
    if (threadIdx.x == 0) {
        __threadfence();
        unsigned gen = g_bar_gen;
        if (atomicAdd(&g_bar_count, 1u) == NBLK - 1) {
            g_bar_count = 0;
            __threadfence();
            g_bar_gen = gen + 1;
        } else {
            while (g_bar_gen == gen) __nanosleep(32);
        }
        __threadfence();
    }
    __syncthreads();
}

__global__ void __launch_bounds__(NT, 1)
sinkhorn_all(const float* __restrict__ x, const float* __restrict__ y,
             const float* __restrict__ Mm,
             float* __restrict__ cost, float* __restrict__ pi,
             float* __restrict__ C)
{
    // smem pool:
    //  gemm/prep: sa = pool[0..4223], sb = pool[4224..8447]
    //  iter:      sv = pool[8192..10239] (scaled v)
    //  fin:       fsu = pool[0..63], fred = pool[1024..2047], sv = pool[8192..]
    __shared__ __align__(16) float pool[11264];
    __shared__ float pmax[2][32], psum[2][32];
    __shared__ float s_err[1];

    float* const sa = pool;
    float* const sb = pool + 4224;
    float* const sv = pool + 8192;

    const int t    = threadIdx.x;
    const int b    = blockIdx.x;
    const int lane = t & 31;
    const int w    = t >> 5;

    // ---- phase 0: zero u, v slice -----------------------------------------
    if (t < 64) {
        g_u[(b << 6) + t] = 0.0f;
        g_v[(b << 6) + t] = 0.0f;
    }

    // ---- phase 1: S = M + M^T ---------------------------------------------
    for (int idx = t; idx < DD * DD; idx += NT) {
        int d = idx >> 6, e = idx & 63;
        sa[idx] = Mm[idx] + Mm[(e << 6) + d];
    }
    __syncthreads();

    // ---- phase 2: XS = x@S, dx = xMx^T, dy = yMy^T ------------------------
    for (int half = 0; half < 2; half++) {
        const float* src = half ? y : x;
        for (int batch = 0; batch < 4; batch++) {
            int row0 = (b << 6) + (batch << 4);
            __syncthreads();
            sb[t] = src[(size_t)row0 * DD + t];
            __syncthreads();
            int slot = t >> 6, e = t & 63;
            float acc = 0.0f;
            #pragma unroll 16
            for (int d = 0; d < DD; d++)
                acc = fmaf(sa[(d << 6) + e], sb[(slot << 6) + d], acc);
            int row = row0 + slot;
            if (!half) g_XS[(size_t)row * DD + e] = acc;
            sb[1024 + t] = acc * sb[(slot << 6) + e];
            __syncthreads();
            for (int off = 32; off > 0; off >>= 1) {
                if (e < off) sb[1024 + (slot << 6) + e] += sb[1024 + (slot << 6) + e + off];
                __syncthreads();
            }
            if (e == 0) {
                float dv = 0.5f * sb[1024 + (slot << 6)];
                if (!half) g_dx[row] = dv; else g_dy[row] = dv;
            }
        }
    }

    grid_bar();

    // ---- phase 3: C build. 128x128 tiles ----------------------------------
    for (int tt = 0; tt < 8; tt++) {
        int tile = b + (tt << 7);
        int n  = tile >> 8;
        int rem = tile & 255;
        int i0 = (rem >> 4) << 7;
        int j0 = (rem & 15) << 7;
        float acc[16];
        #pragma unroll
        for (int q = 0; q < 16; q++) acc[q] = 0.0f;

        #pragma unroll
        for (int ks = 0; ks < 64; ks += 32) {
            __syncthreads();
            {
                int i = t >> 3, kq = t & 7;
                float4 xa = *(const float4*)(g_XS + (size_t)(n * PP + i0 + i) * DD + ks + (kq << 2));
                float4 yb = *(const float4*)(y    + (size_t)(n * PP + j0 + i) * DD + ks + (kq << 2));
                int k0 = kq << 2;
                sa[(k0+0)*132 + i] = xa.x;  sa[(k0+1)*132 + i] = xa.y;
                sa[(k0+2)*132 + i] = xa.z;  sa[(k0+3)*132 + i] = xa.w;
                sb[(k0+0)*132 + i] = yb.x;  sb[(k0+1)*132 + i] = yb.y;
                sb[(k0+2)*132 + i] = yb.z;  sb[(k0+3)*132 + i] = yb.w;
            }
            __syncthreads();
            int cx = t & 31, cy = t >> 5;
            #pragma unroll
            for (int k = 0; k < 32; k++) {
                float4 a4 = *(const float4*)&sa[k*132 + (cy << 2)];
                float4 b4 = *(const float4*)&sb[k*132 + (cx << 2)];
                acc[ 0] = fmaf(a4.x, b4.x, acc[ 0]);
                acc[ 1] = fmaf(a4.x, b4.y, acc[ 1]);
                acc[ 2] = fmaf(a4.x, b4.z, acc[ 2]);
                acc[ 3] = fmaf(a4.x, b4.w, acc[ 3]);
                acc[ 4] = fmaf(a4.y, b4.x, acc[ 4]);
                acc[ 5] = fmaf(a4.y, b4.y, acc[ 5]);
                acc[ 6] = fmaf(a4.y, b4.z, acc[ 6]);
                acc[ 7] = fmaf(a4.y, b4.w, acc[ 7]);
                acc[ 8] = fmaf(a4.z, b4.x, acc[ 8]);
                acc[ 9] = fmaf(a4.z, b4.y, acc[ 9]);
                acc[10] = fmaf(a4.z, b4.z, acc[10]);
                acc[11] = fmaf(a4.z, b4.w, acc[11]);
                acc[12] = fmaf(a4.w, b4.x, acc[12]);
                acc[13] = fmaf(a4.w, b4.y, acc[13]);
                acc[14] = fmaf(a4.w, b4.z, acc[14]);
                acc[15] = fmaf(a4.w, b4.w, acc[15]);
            }
        }
        int cx = t & 31, cy = t >> 5;
        float dxr[4], dyr[4];
        #pragma unroll
        for (int q = 0; q < 4; q++) {
            dxr[q] = g_dx[n * PP + i0 + (cy << 2) + q];
            dyr[q] = g_dy[n * PP + j0 + (cx << 2) + q];
        }
        #pragma unroll
        for (int a = 0; a < 4; a++) {
            float4 o;
            o.x = dxr[a] + dyr[0] - acc[(a << 2) + 0];
            o.y = dxr[a] + dyr[1] - acc[(a << 2) + 1];
            o.z = dxr[a] + dyr[2] - acc[(a << 2) + 2];
            o.w = dxr[a] + dyr[3] - acc[(a << 2) + 3];
            *(float4*)(C + (size_t)(n * PP + i0 + (cy << 2) + a) * PP + j0 + (cx << 2)) = o;
        }
    }

    grid_bar();

    // ---- phase 4: Sinkhorn iterations: z in regs, col acc in regs ---------
    const int n_pass = b >> 5;
    const int sub    = b & 31;
    const float4* C4n = (const float4*)(C + ((size_t)n_pass << 22));
    const int rr  = t >> 8;          // row within 4-row band (0..3)
    const int cth = t & 255;         // float4 column-group index
    bool active = true;

    for (int it = 0; it < MAXIT; it++) {
        // stage scaled v2 = v*SCL
        sv[t]        = g_v[(n_pass << 11) + t] * SCL;
        sv[t + 1024] = g_v[(n_pass << 11) + 1024 + t] * SCL;
        __syncthreads();
        const float4* vs4 = (const float4*)sv;
        const float4 va = vs4[cth];          // cols 4cth..4cth+3 (persistent)
        const float4 vb = vs4[cth + 256];    // cols 1024+4cth..  (persistent)

        // 8 persistent column accumulators (this thread's 16-row subset)
        float cm0 = MNEG, cm1 = MNEG, cm2 = MNEG, cm3 = MNEG;
        float cm4 = MNEG, cm5 = MNEG, cm6 = MNEG, cm7 = MNEG;
        float cs0 = 0.f, cs1 = 0.f, cs2 = 0.f, cs3 = 0.f;
        float cs4 = 0.f, cs5 = 0.f, cs6 = 0.f, cs7 = 0.f;

        #pragma unroll 1
        for (int band = 0; band < 16; band++) {
            const int par = band & 1;
            const int r0  = (sub << 6) + (band << 2);
            const float4* Cr = C4n + (size_t)(r0 + rr) * 512;
            float4 ca = Cr[cth];
            float4 cb = Cr[cth + 256];
            float z0 = fmaf(ca.x, -SCL, va.x);
            float z1 = fmaf(ca.y, -SCL, va.y);
            float z2 = fmaf(ca.z, -SCL, va.z);
            float z3 = fmaf(ca.w, -SCL, va.w);
            float z4 = fmaf(cb.x, -SCL, vb.x);
            float z5 = fmaf(cb.y, -SCL, vb.y);
            float z6 = fmaf(cb.z, -SCL, vb.z);
            float z7 = fmaf(cb.w, -SCL, vb.w);
            // ---- exact row max: warp reduce + 8-slot stage ----
            float mloc = fmaxf(fmaxf(fmaxf(z0, z1), fmaxf(z2, z3)),
                               fmaxf(fmaxf(z4, z5), fmaxf(z6, z7)));
            #pragma unroll
            for (int off = 16; off > 0; off >>= 1)
                mloc = fmaxf(mloc, __shfl_xor_sync(0xffffffffu, mloc, off));
            if (lane == 0) pmax[par][w] = mloc;
            __syncthreads();
            const int wb = rr << 3;
            float mr = fmaxf(fmaxf(fmaxf(pmax[par][wb+0], pmax[par][wb+1]),
                                   fmaxf(pmax[par][wb+2], pmax[par][wb+3])),
                             fmaxf(fmaxf(pmax[par][wb+4], pmax[par][wb+5]),
                                   fmaxf(pmax[par][wb+6], pmax[par][wb+7])));
            // ---- row sum on exact basis ----
            float sloc = ((ex2f(z0 - mr) + ex2f(z1 - mr)) + (ex2f(z2 - mr) + ex2f(z3 - mr)))
                       + ((ex2f(z4 - mr) + ex2f(z5 - mr)) + (ex2f(z6 - mr) + ex2f(z7 - mr)));
            #pragma unroll
            for (int off = 16; off > 0; off >>= 1)
                sloc += __shfl_xor_sync(0xffffffffu, sloc, off);
            if (lane == 0) psum[par][w] = sloc;
            __syncthreads();
            float sr = ((psum[par][wb+0] + psum[par][wb+1]) + (psum[par][wb+2] + psum[par][wb+3]))
                     + ((psum[par][wb+4] + psum[par][wb+5]) + (psum[par][wb+6] + psum[par][wb+7]));
            // redundant per-thread u_new (deterministic: same inputs/ops)
            float unew = UC0 - ELN2 * (mr + __log2f(sr));
            if (cth == 0) {
                int gr = (n_pass << 11) + r0 + rr;
                g_duabs[gr] = fabsf(unew - g_u[gr]);
                g_u[gr] = unew;
            }
            float u2 = unew * SCL;
            // ---- col accumulate from registers (1 ex2/elem, safe basis) ----
            col_acc(cm0, cs0, z0 + u2);
            col_acc(cm1, cs1, z1 + u2);
            col_acc(cm2, cs2, z2 + u2);
            col_acc(cm3, cs3, z3 + u2);
            col_acc(cm4, cs4, z4 + u2);
            col_acc(cm5, cs5, z5 + u2);
            col_acc(cm6, cs6, z6 + u2);
            col_acc(cm7, cs7, z7 + u2);
        }
        // write col partials [n][col][slot], slot = sub*4 + rr (all distinct!)
        {
            const int slot = (sub << 2) + rr;
            size_t cbase = ((size_t)(n_pass << 11) + (cth << 2)) << 7;
            float2 p;
            p.x = cm0; p.y = cs0; g_pms[cbase + (0 << 7) + slot] = p;
            p.x = cm1; p.y = cs1; g_pms[cbase + (1 << 7) + slot] = p;
            p.x = cm2; p.y = cs2; g_pms[cbase + (2 << 7) + slot] = p;
            p.x = cm3; p.y = cs3; g_pms[cbase + (3 << 7) + slot] = p;
            size_t cbase2 = cbase + ((size_t)1024 << 7);
            p.x = cm4; p.y = cs4; g_pms[cbase2 + (0 << 7) + slot] = p;
            p.x = cm5; p.y = cs5; g_pms[cbase2 + (1 << 7) + slot] = p;
            p.x = cm6; p.y = cs6; g_pms[cbase2 + (2 << 7) + slot] = p;
            p.x = cm7; p.y = cs7; g_pms[cbase2 + (3 << 7) + slot] = p;
        }
        grid_bar();

        // ===== merge: warp per column, 128 partials = 4/lane coalesced =====
        {
            int j0 = sub << 6;
            #pragma unroll
            for (int rep = 0; rep < 2; rep++) {
                int col = j0 + w + (rep << 5);
                const float2* p = g_pms + (((size_t)(n_pass << 11) + col) << 7);
                float mm = MNEG, ss = 0.0f;
                #pragma unroll
                for (int q = 0; q < 4; q++) {
                    float2 pv = p[(lane << 2) + q];
                    lse_merge2(mm, ss, pv.x, pv.y);
                }
                #pragma unroll
                for (int off = 16; off > 0; off >>= 1) {
                    float mo = __shfl_xor_sync(0xffffffffu, mm, off);
                    float so = __shfl_xor_sync(0xffffffffu, ss, off);
                    lse_merge2(mm, ss, mo, so);
                }
                if (lane == 0) {
                    int gc = (n_pass << 11) + col;
                    // partials on (z + u2) basis = true xi + v2_j
                    g_v[gc] = UC0 - ELN2 * (mm + __log2f(ss)) + g_v[gc];
                }
            }
        }

        // ===== convergence: shuffle-based replicated reduction =============
        {
            float ea = 0.0f;
            #pragma unroll
            for (int q = 0; q < 8; q++) ea += g_duabs[t + (q << 10)];
            #pragma unroll
            for (int off = 16; off > 0; off >>= 1)
                ea += __shfl_xor_sync(0xffffffffu, ea, off);
            if (lane == 0) pmax[0][w] = ea;
            __syncthreads();
            if (w == 0) {
                float v2 = pmax[0][lane];
                #pragma unroll
                for (int off = 16; off > 0; off >>= 1)
                    v2 += __shfl_xor_sync(0xffffffffu, v2, off);
                if (lane == 0) s_err[0] = v2;
            }
            __syncthreads();
            active = (s_err[0] * 0.25f >= THRESHV);
        }
        grid_bar();
        if (!active) break;
    }

    // ---- phase 5: pi = exp2(u2+v2-C*SCL), cost partials --------------------
    {
        float* fsu  = pool;          // 64 floats
        float* fred = pool + 1024;   // 1024 floats
        sv[t]        = g_v[(n_pass << 11) + t] * SCL;
        sv[t + 1024] = g_v[(n_pass << 11) + 1024 + t] * SCL;
        if (t < 64) fsu[t] = g_u[(n_pass << 11) + (sub << 6) + t] * SCL;
        __syncthreads();
        const float4* vs4 = (const float4*)sv;
        const float4* Cb4 = C4n + (size_t)(sub << 6) * 512;
        float4* pi4 = (float4*)pi + (size_t)(n_pass * PP + (sub << 6)) * 512;
        float accc = 0.0f;
        #pragma unroll 4
        for (int k2 = 0; k2 < 32; k2++) {
            int idx = t + (k2 << 10);
            int row = idx >> 9;
            int c4  = idx & 511;
            float4 cc = Cb4[(size_t)row * 512 + c4];
            float  uu = fsu[row];
            float4 vv = vs4[c4];
            float p0 = ex2f(fmaf(cc.x, -SCL, uu + vv.x));
            float p1 = ex2f(fmaf(cc.y, -SCL, uu + vv.y));
            float p2 = ex2f(fmaf(cc.z, -SCL, uu + vv.z));
            float p3 = ex2f(fmaf(cc.w, -SCL, uu + vv.w));
            float4 po; po.x = p0; po.y = p1; po.z = p2; po.w = p3;
            pi4[(size_t)row * 512 + c4] = po;
            accc = fmaf(p0, cc.x, accc);
            accc = fmaf(p1, cc.y, accc);
            accc = fmaf(p2, cc.z, accc);
            accc = fmaf(p3, cc.w, accc);
        }
        __syncthreads();
        fred[t] = accc;
        __syncthreads();
        for (int off = 512; off > 0; off >>= 1) {
            if (t < off) fred[t] += fred[t + off];
            __syncthreads();
        }
        if (t == 0) g_cpart[b] = fred[0];
    }
    grid_bar();
    if (b == 0 && t == 0) {
        #pragma unroll
        for (int n = 0; n < NB; n++) {
            float c = 0.0f;
            for (int q = 0; q < 32; q++) c += g_cpart[(n << 5) + q];
            cost[n] = c;
        }
    }
}

// ---------------- launch ---------------------------------------------------
extern "C" void kernel_launch(void* const* d_in, const int* in_sizes, int n_in,
                              void* d_out, int out_size) {
    const float* x = (const float*)d_in[0];   // [N,P1,D]
    const float* y = (const float*)d_in[1];   // [N,P2,D]
    const float* M = (const float*)d_in[2];   // [D,D]
    float* out  = (float*)d_out;              // cost[4] | pi | C
    float* cost = out;
    float* pi   = out + 4;
    float* C    = out + 4 + (size_t)NPITEMS;

    sinkhorn_all<<<NBLK, NT>>>(x, y, M, cost, pi, C);
}

// round 14
// speedup vs baseline: 1.5831x; 1.5626x over previous
#include <cuda_runtime.h>
#include <math.h>

// Problem constants: N=4, P1=P2=2048, D=64
#define NB 4
#define PP 2048
#define DD 64
#define SCL      14.426950408889634f   // INV_EPS * log2(e)
#define ELN2     0.0693147180559945f   // EPSR * ln(2)
#define UC0      (-0.76245985f)        // EPSR * log(1/2048 + 1e-8)
#define THRESHV  0.1f
#define MAXIT    50
#define NBLK     128
#define NT       1024
#define NPITEMS  (NB * PP * PP)
#define MNEG     (-3.402823466e38f)

// ---------------- device scratch (no allocations allowed) ------------------
__device__ float g_XS[NB * PP * DD];     // x @ (M+M^T)
__device__ float g_dx[NB * PP];
__device__ float g_dy[NB * PP];
__device__ float g_u[NB * PP];
__device__ float g_v[NB * PP];
__device__ float g_duabs[NB * PP];
__device__ float2 g_pms[NB * PP * 32];   // col partials [n][col][block] = (m,s)
__device__ float g_cpart[NBLK];
__device__ unsigned g_bar_count;
__device__ volatile unsigned g_bar_gen;

__device__ __forceinline__ float ex2f(float x) {
    float r;
    asm("ex2.approx.ftz.f32 %0, %1;" : "=f"(r) : "f"(x));
    return r;
}

// online-LSE merge in log2 domain, single ex2
__device__ __forceinline__ void lse_merge2(float& m, float& s, float mc, float sc) {
    float mmax = fmaxf(m, mc);
    float e = ex2f(fminf(m, mc) - mmax);
    s = (m >= mc) ? fmaf(sc, e, s) : fmaf(s, e, sc);
    m = mmax;
}

// ---------------- software grid barrier (proven: R2-R11) -------------------
__device__ __forceinline__ void grid_bar() {
    __syncthreads();
    if (threadIdx.x == 0) {
        __threadfence();
        unsigned gen = g_bar_gen;
        if (atomicAdd(&g_bar_count, 1u) == NBLK - 1) {
            g_bar_count = 0;
            __threadfence();
            g_bar_gen = gen + 1;
        } else {
            while (g_bar_gen == gen) __nanosleep(32);
        }
        __threadfence();
    }
    __syncthreads();
}

__global__ void __launch_bounds__(NT, 1)
sinkhorn_all(const float* __restrict__ x, const float* __restrict__ y,
             const float* __restrict__ Mm,
             float* __restrict__ cost, float* __restrict__ pi,
             float* __restrict__ C)
{
    __shared__ __align__(16) float sv[PP];      // scaled v (8KB)
    __shared__ __align__(16) float sa[4224];
    __shared__ __align__(16) float sb[4224];
    __shared__ float su[16];                    // scaled u_new for band
    __shared__ float pm2m[32], pm2s[32];        // per-warp row partials
    __shared__ float s_err[1];

    const int t    = threadIdx.x;
    const int b    = blockIdx.x;
    const int lane = t & 31;
    const int w    = t >> 5;

    // ---- phase 0: zero u, v slice -----------------------------------------
    if (t < 64) {
        g_u[(b << 6) + t] = 0.0f;
        g_v[(b << 6) + t] = 0.0f;
    }

    // ---- phase 1: S = M + M^T ---------------------------------------------
    for (int idx = t; idx < DD * DD; idx += NT) {
        int d = idx >> 6, e = idx & 63;
        sa[idx] = Mm[idx] + Mm[(e << 6) + d];
    }
    __syncthreads();

    // ---- phase 2: XS = x@S, dx = xMx^T, dy = yMy^T ------------------------
    for (int half = 0; half < 2; half++) {
        const float* src = half ? y : x;
        for (int batch = 0; batch < 4; batch++) {
            int row0 = (b << 6) + (batch << 4);
            __syncthreads();
            sb[t] = src[(size_t)row0 * DD + t];
            __syncthreads();
            int slot = t >> 6, e = t & 63;
            float acc = 0.0f;
            #pragma unroll 16
            for (int d = 0; d < DD; d++)
                acc = fmaf(sa[(d << 6) + e], sb[(slot << 6) + d], acc);
            int row = row0 + slot;
            if (!half) g_XS[(size_t)row * DD + e] = acc;
            sb[1024 + t] = acc * sb[(slot << 6) + e];
            __syncthreads();
            for (int off = 32; off > 0; off >>= 1) {
                if (e < off) sb[1024 + (slot << 6) + e] += sb[1024 + (slot << 6) + e + off];
                __syncthreads();
            }
            if (e == 0) {
                float dv = 0.5f * sb[1024 + (slot << 6)];
                if (!half) g_dx[row] = dv; else g_dy[row] = dv;
            }
        }
    }

    grid_bar();

    // ---- phase 3: C build. 128x128 tiles ----------------------------------
    for (int tt = 0; tt < 8; tt++) {
        int tile = b + (tt << 7);
        int n  = tile >> 8;
        int rem = tile & 255;
        int i0 = (rem >> 4) << 7;
        int j0 = (rem & 15) << 7;
        float acc[16];
        #pragma unroll
        for (int q = 0; q < 16; q++) acc[q] = 0.0f;

        #pragma unroll
        for (int ks = 0; ks < 64; ks += 32) {
            __syncthreads();
            {
                int i = t >> 3, kq = t & 7;
                float4 xa = *(const float4*)(g_XS + (size_t)(n * PP + i0 + i) * DD + ks + (kq << 2));
                float4 yb = *(const float4*)(y    + (size_t)(n * PP + j0 + i) * DD + ks + (kq << 2));
                int k0 = kq << 2;
                sa[(k0+0)*132 + i] = xa.x;  sa[(k0+1)*132 + i] = xa.y;
                sa[(k0+2)*132 + i] = xa.z;  sa[(k0+3)*132 + i] = xa.w;
                sb[(k0+0)*132 + i] = yb.x;  sb[(k0+1)*132 + i] = yb.y;
                sb[(k0+2)*132 + i] = yb.z;  sb[(k0+3)*132 + i] = yb.w;
            }
            __syncthreads();
            int cx = t & 31, cy = t >> 5;
            #pragma unroll
            for (int k = 0; k < 32; k++) {
                float4 a4 = *(const float4*)&sa[k*132 + (cy << 2)];
                float4 b4 = *(const float4*)&sb[k*132 + (cx << 2)];
                acc[ 0] = fmaf(a4.x, b4.x, acc[ 0]);
                acc[ 1] = fmaf(a4.x, b4.y, acc[ 1]);
                acc[ 2] = fmaf(a4.x, b4.z, acc[ 2]);
                acc[ 3] = fmaf(a4.x, b4.w, acc[ 3]);
                acc[ 4] = fmaf(a4.y, b4.x, acc[ 4]);
                acc[ 5] = fmaf(a4.y, b4.y, acc[ 5]);
                acc[ 6] = fmaf(a4.y, b4.z, acc[ 6]);
                acc[ 7] = fmaf(a4.y, b4.w, acc[ 7]);
                acc[ 8] = fmaf(a4.z, b4.x, acc[ 8]);
                acc[ 9] = fmaf(a4.z, b4.y, acc[ 9]);
                acc[10] = fmaf(a4.z, b4.z, acc[10]);
                acc[11] = fmaf(a4.z, b4.w, acc[11]);
                acc[12] = fmaf(a4.w, b4.x, acc[12]);
                acc[13] = fmaf(a4.w, b4.y, acc[13]);
                acc[14] = fmaf(a4.w, b4.z, acc[14]);
                acc[15] = fmaf(a4.w, b4.w, acc[15]);
            }
        }
        int cx = t & 31, cy = t >> 5;
        float dxr[4], dyr[4];
        #pragma unroll
        for (int q = 0; q < 4; q++) {
            dxr[q] = g_dx[n * PP + i0 + (cy << 2) + q];
            dyr[q] = g_dy[n * PP + j0 + (cx << 2) + q];
        }
        #pragma unroll
        for (int a = 0; a < 4; a++) {
            float4 o;
            o.x = dxr[a] + dyr[0] - acc[(a << 2) + 0];
            o.y = dxr[a] + dyr[1] - acc[(a << 2) + 1];
            o.z = dxr[a] + dyr[2] - acc[(a << 2) + 2];
            o.w = dxr[a] + dyr[3] - acc[(a << 2) + 3];
            *(float4*)(C + (size_t)(n * PP + i0 + (cy << 2) + a) * PP + j0 + (cx << 2)) = o;
        }
    }

    grid_bar();

    // ---- phase 4: Sinkhorn iterations, fused single-C-read ----------------
    const int n_pass = b >> 5;
    const int sub    = b & 31;
    const float* Cn  = C + ((size_t)n_pass << 22);
    bool active = true;

    for (int it = 0; it < MAXIT; it++) {
        // stage scaled v
        sv[t]        = g_v[(n_pass << 11) + t] * SCL;
        sv[t + 1024] = g_v[(n_pass << 11) + 1024 + t] * SCL;
        __syncthreads();

        const float4* vs4 = (const float4*)sv;
        float cm0 = MNEG, cs0 = 0.0f;    // column accumulators: cols 2t, 2t+1
        float cm1 = MNEG, cs1 = 0.0f;

        #pragma unroll 1
        for (int band = 0; band < 4; band++) {
            int r0 = (sub << 6) + (band << 4);
            // ===== row phase: 16 rows x 64 threads, stream C from L2 ======
            {
                int rr  = t >> 6;         // row within band (0..15)
                int cth = t & 63;         // thread within row
                const float4* Cr = (const float4*)Cn + (size_t)(r0 + rr) * 512;
                float m = MNEG, s = 0.0f;
                float4 ca = Cr[cth];
                float4 cb = Cr[cth + 64];
                #pragma unroll
                for (int k = 0; k < 4; k++) {
                    float4 na, nb;
                    if (k < 3) {
                        na = Cr[cth + (k << 7) + 128];
                        nb = Cr[cth + (k << 7) + 192];
                    }
                    float4 va = vs4[cth + (k << 7)];
                    float4 vb = vs4[cth + (k << 7) + 64];
                    float z0 = fmaf(ca.x, -SCL, va.x);
                    float z1 = fmaf(ca.y, -SCL, va.y);
                    float z2 = fmaf(ca.z, -SCL, va.z);
                    float z3 = fmaf(ca.w, -SCL, va.w);
                    float z4 = fmaf(cb.x, -SCL, vb.x);
                    float z5 = fmaf(cb.y, -SCL, vb.y);
                    float z6 = fmaf(cb.z, -SCL, vb.z);
                    float z7 = fmaf(cb.w, -SCL, vb.w);
                    float mc = fmaxf(fmaxf(fmaxf(z0, z1), fmaxf(z2, z3)),
                                     fmaxf(fmaxf(z4, z5), fmaxf(z6, z7)));
                    float sc = ex2f(z0 - mc) + ex2f(z1 - mc)
                             + ex2f(z2 - mc) + ex2f(z3 - mc)
                             + ex2f(z4 - mc) + ex2f(z5 - mc)
                             + ex2f(z6 - mc) + ex2f(z7 - mc);
                    lse_merge2(m, s, mc, sc);
                    ca = na; cb = nb;
                }
                #pragma unroll
                for (int off = 16; off > 0; off >>= 1) {
                    float mo = __shfl_xor_sync(0xffffffffu, m, off);
                    float so = __shfl_xor_sync(0xffffffffu, s, off);
                    lse_merge2(m, s, mo, so);
                }
                if (lane == 0) { pm2m[w] = m; pm2s[w] = s; }
            }
            __syncthreads();
            if (t < 16) {
                float M = pm2m[t << 1],       S = pm2s[t << 1];
                lse_merge2(M, S, pm2m[(t << 1) + 1], pm2s[(t << 1) + 1]);
                float unew = UC0 - ELN2 * (M + __log2f(S));
                int gr = (n_pass << 11) + r0 + t;
                g_duabs[gr] = fabsf(unew - g_u[gr]);
                g_u[gr] = unew;
                su[t] = unew * SCL;
            }
            __syncthreads();
            // ===== column phase: re-read band from L1, cols (2t, 2t+1) ====
            {
                const float2* Cc2 = (const float2*)(Cn + (size_t)r0 * PP);
                #pragma unroll
                for (int half = 0; half < 2; half++) {
                    int rb = half << 3;
                    float z[8], zz[8];
                    #pragma unroll
                    for (int q = 0; q < 8; q++) {
                        float uq = su[rb + q];
                        float2 c2 = Cc2[(size_t)(rb + q) * 1024 + t];
                        z[q]  = fmaf(c2.x, -SCL, uq);
                        zz[q] = fmaf(c2.y, -SCL, uq);
                    }
                    float mc = fmaxf(fmaxf(fmaxf(z[0], z[1]), fmaxf(z[2], z[3])),
                                     fmaxf(fmaxf(z[4], z[5]), fmaxf(z[6], z[7])));
                    float sc = ex2f(z[0]-mc) + ex2f(z[1]-mc) + ex2f(z[2]-mc) + ex2f(z[3]-mc)
                             + ex2f(z[4]-mc) + ex2f(z[5]-mc) + ex2f(z[6]-mc) + ex2f(z[7]-mc);
                    lse_merge2(cm0, cs0, mc, sc);
                    float mc2 = fmaxf(fmaxf(fmaxf(zz[0], zz[1]), fmaxf(zz[2], zz[3])),
                                      fmaxf(fmaxf(zz[4], zz[5]), fmaxf(zz[6], zz[7])));
                    float sc2 = ex2f(zz[0]-mc2) + ex2f(zz[1]-mc2) + ex2f(zz[2]-mc2) + ex2f(zz[3]-mc2)
                              + ex2f(zz[4]-mc2) + ex2f(zz[5]-mc2) + ex2f(zz[6]-mc2) + ex2f(zz[7]-mc2);
                    lse_merge2(cm1, cs1, mc2, sc2);
                }
            }
        }
        // write column partials, transposed layout [n][col][block]
        {
            size_t base = ((size_t)(n_pass << 11) + (t << 1)) << 5;   // col 2t
            float2 p0; p0.x = cm0; p0.y = cs0;
            float2 p1; p1.x = cm1; p1.y = cs1;
            g_pms[base + sub]      = p0;   // col 2t
            g_pms[base + 32 + sub] = p1;   // col 2t+1
        }
        grid_bar();

        // ===== merge: warp per column, coalesced reads + shuffle tree ======
        {
            int j0 = sub << 6;
            #pragma unroll
            for (int rep = 0; rep < 2; rep++) {
                int col = j0 + w + (rep << 5);
                float2 p = g_pms[(((size_t)(n_pass << 11) + col) << 5) + lane];
                float mm = p.x, ss = p.y;
                #pragma unroll
                for (int off = 16; off > 0; off >>= 1) {
                    float mo = __shfl_xor_sync(0xffffffffu, mm, off);
                    float so = __shfl_xor_sync(0xffffffffu, ss, off);
                    lse_merge2(mm, ss, mo, so);
                }
                if (lane == 0)
                    g_v[(n_pass << 11) + col] = UC0 - ELN2 * (mm + __log2f(ss));
            }
        }

        // ===== convergence: shuffle-based replicated reduction =============
        {
            float ea = 0.0f;
            #pragma unroll
            for (int q = 0; q < 8; q++) ea += g_duabs[t + (q << 10)];
            #pragma unroll
            for (int off = 16; off > 0; off >>= 1)
                ea += __shfl_xor_sync(0xffffffffu, ea, off);
            if (lane == 0) pm2m[w] = ea;
            __syncthreads();
            if (w == 0) {
                float v2 = pm2m[lane];
                #pragma unroll
                for (int off = 16; off > 0; off >>= 1)
                    v2 += __shfl_xor_sync(0xffffffffu, v2, off);
                if (lane == 0) s_err[0] = v2;
            }
            __syncthreads();
            active = (s_err[0] * 0.25f >= THRESHV);
        }
        grid_bar();
        if (!active) break;
    }

    // ---- phase 5: pi = exp2(u2+v2-C*SCL), cost partials --------------------
    {
        const float4* C4n = (const float4*)Cn;
        sv[t]        = g_v[(n_pass << 11) + t] * SCL;
        sv[t + 1024] = g_v[(n_pass << 11) + 1024 + t] * SCL;
        if (t < 64) sa[t] = g_u[(n_pass << 11) + (sub << 6) + t] * SCL;
        __syncthreads();
        const float4* vs4 = (const float4*)sv;
        const float4* Cb4 = C4n + (size_t)(sub << 6) * 512;
        float4* pi4 = (float4*)pi + (size_t)(n_pass * PP + (sub << 6)) * 512;
        float accc = 0.0f;
        #pragma unroll 4
        for (int k2 = 0; k2 < 32; k2++) {
            int idx = t + (k2 << 10);
            int row = idx >> 9;
            int c4  = idx & 511;
            float4 cc = Cb4[(size_t)row * 512 + c4];
            float  uu = sa[row];
            float4 vv = vs4[c4];
            float p0 = ex2f(fmaf(cc.x, -SCL, uu + vv.x));
            float p1 = ex2f(fmaf(cc.y, -SCL, uu + vv.y));
            float p2 = ex2f(fmaf(cc.z, -SCL, uu + vv.z));
            float p3 = ex2f(fmaf(cc.w, -SCL, uu + vv.w));
            float4 po; po.x = p0; po.y = p1; po.z = p2; po.w = p3;
            pi4[(size_t)row * 512 + c4] = po;
            accc = fmaf(p0, cc.x, accc);
            accc = fmaf(p1, cc.y, accc);
            accc = fmaf(p2, cc.z, accc);
            accc = fmaf(p3, cc.w, accc);
        }
        __syncthreads();
        sb[t] = accc;
        __syncthreads();
        for (int off = 512; off > 0; off >>= 1) {
            if (t < off) sb[t] += sb[t + off];
            __syncthreads();
        }
        if (t == 0) g_cpart[b] = sb[0];
    }
    grid_bar();
    if (b == 0 && t == 0) {
        #pragma unroll
        for (int n = 0; n < NB; n++) {
            float c = 0.0f;
            for (int q = 0; q < 32; q++) c += g_cpart[(n << 5) + q];
            cost[n] = c;
        }
    }
}

// ---------------- launch ---------------------------------------------------
extern "C" void kernel_launch(void* const* d_in, const int* in_sizes, int n_in,
                              void* d_out, int out_size) {
    const float* x = (const float*)d_in[0];   // [N,P1,D]
    const float* y = (const float*)d_in[1];   // [N,P2,D]
    const float* M = (const float*)d_in[2];   // [D,D]
    float* out  = (float*)d_out;              // cost[4] | pi | C
    float* cost = out;
    float* pi   = out + 4;
    float* C    = out + 4 + (size_t)NPITEMS;

    sinkhorn_all<<<NBLK, NT>>>(x, y, M, cost, pi, C);
}